// round 9
// baseline (speedup 1.0000x reference)
#include <cuda_runtime.h>

// WaveLetPooling: input (8, 512, 512, 64) fp32 NHWC.
// Output: [ll | lh | hl | hh], each (8, 256, 256, 64), concatenated in d_out.
//
// 256-bit accesses (LDG.E.256/STG.E.256, sm_10x) + butterfly-factored
// Haar + 128-thread blocks (32768 independent CTAs — the work-distribution
// granularity that measured best DRAM%). Traffic is minimal (1.07 GB);
// kernel is HBM-bound at ~6.8 TB/s.

#define N_  8u
#define H_  512u
#define W_  512u
#define C_  64u
#define HO  (H_/2u)       // 256
#define WO  (W_/2u)       // 256
#define C8  (C_/8u)       // 8 f8-groups per position
#define Q8  (N_*HO*WO*C8) // f8 per quadrant = 4,194,304

struct __align__(32) f8 { float4 lo, hi; };

__device__ __forceinline__ f8 f8add(const f8& x, const f8& y) {
    f8 r;
    r.lo.x = x.lo.x + y.lo.x; r.lo.y = x.lo.y + y.lo.y;
    r.lo.z = x.lo.z + y.lo.z; r.lo.w = x.lo.w + y.lo.w;
    r.hi.x = x.hi.x + y.hi.x; r.hi.y = x.hi.y + y.hi.y;
    r.hi.z = x.hi.z + y.hi.z; r.hi.w = x.hi.w + y.hi.w;
    return r;
}
__device__ __forceinline__ f8 f8sub(const f8& x, const f8& y) {
    f8 r;
    r.lo.x = x.lo.x - y.lo.x; r.lo.y = x.lo.y - y.lo.y;
    r.lo.z = x.lo.z - y.lo.z; r.lo.w = x.lo.w - y.lo.w;
    r.hi.x = x.hi.x - y.hi.x; r.hi.y = x.hi.y - y.hi.y;
    r.hi.z = x.hi.z - y.hi.z; r.hi.w = x.hi.w - y.hi.w;
    return r;
}
__device__ __forceinline__ f8 f8half(const f8& x) {
    f8 r;
    r.lo.x = 0.5f * x.lo.x; r.lo.y = 0.5f * x.lo.y;
    r.lo.z = 0.5f * x.lo.z; r.lo.w = 0.5f * x.lo.w;
    r.hi.x = 0.5f * x.hi.x; r.hi.y = 0.5f * x.hi.y;
    r.hi.z = 0.5f * x.hi.z; r.hi.w = 0.5f * x.hi.w;
    return r;
}

__global__ __launch_bounds__(128) void wavelet_pool_kernel(
    const f8* __restrict__ in, f8* __restrict__ out)
{
    unsigned tid = blockIdx.x * blockDim.x + threadIdx.x;
    // tid -> (n, ho, wo, c8): c8 in [0,8), wo in [0,256), ho in [0,256), n in [0,8)
    unsigned c8 = tid & 7u;
    unsigned wo = (tid >> 3) & 255u;
    unsigned ho = (tid >> 11) & 255u;
    unsigned n  = tid >> 19;

    unsigned ibase = ((n * H_ + 2u * ho) * W_ + 2u * wo) * C8 + c8;
    const unsigned ROW8 = W_ * C8;  // 4096 f8 per input row

    f8 a = in[ibase];
    f8 b = in[ibase + C8];
    f8 c = in[ibase + ROW8];
    f8 d = in[ibase + ROW8 + C8];

    // butterfly: s0=a+b, d0=b-a, s1=c+d, d1=d-c
    f8 s0 = f8add(a, b);
    f8 d0 = f8sub(b, a);
    f8 s1 = f8add(c, d);
    f8 d1 = f8sub(d, c);

    f8 ll = f8half(f8add(s0, s1));  //  a+b+c+d
    f8 lh = f8half(f8add(d0, d1));  // -a+b-c+d
    f8 hl = f8half(f8sub(s1, s0));  // -a-b+c+d
    f8 hh = f8half(f8sub(d1, d0));  //  a-b-c+d

    unsigned o = ((n * HO + ho) * WO + wo) * C8 + c8;
    out[o]          = ll;
    out[o + Q8]     = lh;
    out[o + 2u*Q8]  = hl;
    out[o + 3u*Q8]  = hh;
}

extern "C" void kernel_launch(void* const* d_in, const int* in_sizes, int n_in,
                              void* d_out, int out_size)
{
    const f8* in  = (const f8*)d_in[0];
    f8*       out = (f8*)d_out;

    const unsigned total = Q8;             // 4,194,304 threads
    const unsigned block = 128;
    const unsigned grid  = total / block;  // 32768
    wavelet_pool_kernel<<<grid, block>>>(in, out);
}

// round 10
// speedup vs baseline: 1.0004x; 1.0004x over previous
#include <cuda_runtime.h>

// WaveLetPooling: input (8, 512, 512, 64) fp32 NHWC.
// a = in[:,0::2,0::2,:], b = in[:,0::2,1::2,:], c = in[:,1::2,0::2,:], d = in[:,1::2,1::2,:]
// ll = .5(a+b+c+d); lh = .5(-a+b-c+d); hl = .5(-a-b+c+d); hh = .5(a-b-c+d)
// Output: [ll | lh | hl | hh], each (8, 256, 256, 64), concatenated in d_out.
//
// FINAL — best measured configuration over a 9-round sweep.
// Pure streaming op (537 MB read + 537 MB write, zero reuse) running at
// the chip's achieved HBM ceiling: 6.8 TB/s = ~85-86% of 8 TB/s spec for
// a 1:1 R/W mix. Swept and within-noise: vector width (128 vs 256-bit),
// block size (128/256/512), grid (16k/32k CTAs), cache hints (.cs),
// FMA vs butterfly arithmetic, 1 vs 2 positions/thread. Rejected:
// persistent single-wave grid (-10%, starves the memory request pool).
// This variant: 256-bit LDG/STG (two adjacent c4 slots per thread),
// 256-thread blocks, default caching, FFMA-imm arithmetic.

#define N_  8u
#define H_  512u
#define W_  512u
#define C_  64u
#define HO  (H_/2u)       // 256
#define WO  (W_/2u)       // 256
#define C8  (C_/8u)       // 8 f8-groups per position
#define Q4  (N_*HO*WO*(C_/4u)) // float4 per quadrant = 8,388,608

struct __align__(32) f8 { float4 lo, hi; };

__device__ __forceinline__ f8 haar8(const f8& a, const f8& b,
                                    const f8& c, const f8& d,
                                    float sa, float sb, float sc)
{
    f8 r;
    r.lo.x = 0.5f * (sa*a.lo.x + sb*b.lo.x + sc*c.lo.x + d.lo.x);
    r.lo.y = 0.5f * (sa*a.lo.y + sb*b.lo.y + sc*c.lo.y + d.lo.y);
    r.lo.z = 0.5f * (sa*a.lo.z + sb*b.lo.z + sc*c.lo.z + d.lo.z);
    r.lo.w = 0.5f * (sa*a.lo.w + sb*b.lo.w + sc*c.lo.w + d.lo.w);
    r.hi.x = 0.5f * (sa*a.hi.x + sb*b.hi.x + sc*c.hi.x + d.hi.x);
    r.hi.y = 0.5f * (sa*a.hi.y + sb*b.hi.y + sc*c.hi.y + d.hi.y);
    r.hi.z = 0.5f * (sa*a.hi.z + sb*b.hi.z + sc*c.hi.z + d.hi.z);
    r.hi.w = 0.5f * (sa*a.hi.w + sb*b.hi.w + sc*c.hi.w + d.hi.w);
    return r;
}

__global__ __launch_bounds__(256) void wavelet_pool_kernel(
    const f8* __restrict__ in, f8* __restrict__ out)
{
    unsigned tid = blockIdx.x * blockDim.x + threadIdx.x;
    // tid -> (n, ho, wo, c8): c8 in [0,8), wo in [0,256), ho in [0,256), n in [0,8)
    unsigned c8 = tid & 7u;
    unsigned wo = (tid >> 3) & 255u;
    unsigned ho = (tid >> 11) & 255u;
    unsigned n  = tid >> 19;

    // input f8 index: ((n*H + 2*ho)*W + 2*wo)*C8 + c8
    unsigned ibase = ((n * H_ + 2u * ho) * W_ + 2u * wo) * C8 + c8;
    const unsigned ROW8 = W_ * C8;  // f8 per input row = 4096

    f8 a = in[ibase];
    f8 b = in[ibase + C8];
    f8 c = in[ibase + ROW8];
    f8 d = in[ibase + ROW8 + C8];

    f8 ll = haar8(a, b, c, d,  1.f,  1.f,  1.f);
    f8 lh = haar8(a, b, c, d, -1.f,  1.f, -1.f);
    f8 hl = haar8(a, b, c, d, -1.f, -1.f,  1.f);
    f8 hh = haar8(a, b, c, d,  1.f, -1.f, -1.f);

    const unsigned Q8 = Q4 / 2u;  // f8 per quadrant = 4,194,304
    unsigned o = ((n * HO + ho) * WO + wo) * C8 + c8;
    out[o]          = ll;
    out[o + Q8]     = lh;
    out[o + 2u*Q8]  = hl;
    out[o + 3u*Q8]  = hh;
}

extern "C" void kernel_launch(void* const* d_in, const int* in_sizes, int n_in,
                              void* d_out, int out_size)
{
    const f8* in  = (const f8*)d_in[0];
    f8*       out = (f8*)d_out;

    const unsigned total = Q4 / 2u;        // 4,194,304 threads
    const unsigned block = 256;
    const unsigned grid  = total / block;  // 16384
    wavelet_pool_kernel<<<grid, block>>>(in, out);
}

// round 11
// speedup vs baseline: 1.0065x; 1.0061x over previous
#include <cuda_runtime.h>

// WaveLetPooling: input (8, 512, 512, 64) fp32 NHWC.
// a = in[:,0::2,0::2,:], b = in[:,0::2,1::2,:], c = in[:,1::2,0::2,:], d = in[:,1::2,1::2,:]
// ll = .5(a+b+c+d); lh = .5(-a+b-c+d); hl = .5(-a-b+c+d); hh = .5(a-b-c+d)
// Output: [ll | lh | hl | hh], each (8, 256, 256, 64), concatenated in d_out.
//
// FINAL — roofline-converged over a 10-round sweep (session closed).
// Pure streaming op: 537 MB read + 537 MB write, zero reuse. Runs at the
// chip's achieved HBM ceiling of ~6.8 TB/s (85-86% of 8 TB/s spec for a
// 1:1 R/W mix). Identical-binary reruns established a ±1 us / ±0.5% DRAM
// noise band; all flat-grid variants (vector width, block size, grid
// size, cache hints, arithmetic form, positions/thread) are statistically
// indistinguishable inside it. Persistent single-wave grid was the only
// variant outside the band: -10% (starves the memory request pool).
// This configuration held the best harness time: 256-bit LDG/STG (two
// adjacent float4 slots per thread), 256-thread blocks, 16384 independent
// CTAs, default caching, FFMA-imm arithmetic.

#define N_  8u
#define H_  512u
#define W_  512u
#define C_  64u
#define HO  (H_/2u)       // 256
#define WO  (W_/2u)       // 256
#define C8  (C_/8u)       // 8 f8-groups per position
#define Q4  (N_*HO*WO*(C_/4u)) // float4 per quadrant = 8,388,608

struct __align__(32) f8 { float4 lo, hi; };

__device__ __forceinline__ f8 haar8(const f8& a, const f8& b,
                                    const f8& c, const f8& d,
                                    float sa, float sb, float sc)
{
    f8 r;
    r.lo.x = 0.5f * (sa*a.lo.x + sb*b.lo.x + sc*c.lo.x + d.lo.x);
    r.lo.y = 0.5f * (sa*a.lo.y + sb*b.lo.y + sc*c.lo.y + d.lo.y);
    r.lo.z = 0.5f * (sa*a.lo.z + sb*b.lo.z + sc*c.lo.z + d.lo.z);
    r.lo.w = 0.5f * (sa*a.lo.w + sb*b.lo.w + sc*c.lo.w + d.lo.w);
    r.hi.x = 0.5f * (sa*a.hi.x + sb*b.hi.x + sc*c.hi.x + d.hi.x);
    r.hi.y = 0.5f * (sa*a.hi.y + sb*b.hi.y + sc*c.hi.y + d.hi.y);
    r.hi.z = 0.5f * (sa*a.hi.z + sb*b.hi.z + sc*c.hi.z + d.hi.z);
    r.hi.w = 0.5f * (sa*a.hi.w + sb*b.hi.w + sc*c.hi.w + d.hi.w);
    return r;
}

__global__ __launch_bounds__(256) void wavelet_pool_kernel(
    const f8* __restrict__ in, f8* __restrict__ out)
{
    unsigned tid = blockIdx.x * blockDim.x + threadIdx.x;
    // tid -> (n, ho, wo, c8): c8 in [0,8), wo in [0,256), ho in [0,256), n in [0,8)
    unsigned c8 = tid & 7u;
    unsigned wo = (tid >> 3) & 255u;
    unsigned ho = (tid >> 11) & 255u;
    unsigned n  = tid >> 19;

    // input f8 index: ((n*H + 2*ho)*W + 2*wo)*C8 + c8
    unsigned ibase = ((n * H_ + 2u * ho) * W_ + 2u * wo) * C8 + c8;
    const unsigned ROW8 = W_ * C8;  // f8 per input row = 4096

    f8 a = in[ibase];
    f8 b = in[ibase + C8];
    f8 c = in[ibase + ROW8];
    f8 d = in[ibase + ROW8 + C8];

    f8 ll = haar8(a, b, c, d,  1.f,  1.f,  1.f);
    f8 lh = haar8(a, b, c, d, -1.f,  1.f, -1.f);
    f8 hl = haar8(a, b, c, d, -1.f, -1.f,  1.f);
    f8 hh = haar8(a, b, c, d,  1.f, -1.f, -1.f);

    const unsigned Q8 = Q4 / 2u;  // f8 per quadrant = 4,194,304
    unsigned o = ((n * HO + ho) * WO + wo) * C8 + c8;
    out[o]          = ll;
    out[o + Q8]     = lh;
    out[o + 2u*Q8]  = hl;
    out[o + 3u*Q8]  = hh;
}

extern "C" void kernel_launch(void* const* d_in, const int* in_sizes, int n_in,
                              void* d_out, int out_size)
{
    const f8* in  = (const f8*)d_in[0];
    f8*       out = (f8*)d_out;

    const unsigned total = Q4 / 2u;        // 4,194,304 threads
    const unsigned block = 256;
    const unsigned grid  = total / block;  // 16384
    wavelet_pool_kernel<<<grid, block>>>(in, out);
}